// round 5
// baseline (speedup 1.0000x reference)
#include <cuda_runtime.h>
#include <cuda_bf16.h>

// FieldAwareFM: out[b] = sum over 780 field pairs (a<b) of
//   dot(x[b, a, b-1, :], x[b, b, a, :]),  x = input reshaped (bs, 40, 39, 16).
//
// R5: SMEM-staged. The DRAM-facing stream is now a PURE sequential copy of
// each 97.5 KB row into shared memory via cp.async (LDGSTS, no register
// staging, unbounded depth). The irregular pair gather happens in SMEM.
// R2-R4 showed the gather-style LDG stream caps HBM at ~5.6 TB/s while the
// chip sustains 6.4+ TB/s on sequential streams; staging separates the two.
//
// One block per row; 2 blocks/SM (smem-limited) alternate load/compute so
// DRAM stays busy. Pair table is built (ALU only) while cp.asyncs fly.

#define NUM_FIELDS 40
#define COLS 39
#define EMB 16
#define ROW_FLOATS (NUM_FIELDS * COLS * EMB)      // 24960
#define ROW_F4 (ROW_FLOATS / 4)                   // 6240
#define ROW_BYTES (ROW_F4 * 16)                   // 99840
#define NPAIRS 780
#define WORK (NPAIRS * 4)                         // 3120 float4-pair items
#define THREADS 256
#define LOAD_ITERS (ROW_F4 / THREADS)             // 24
#define LOAD_REM (ROW_F4 - LOAD_ITERS * THREADS)  // 96
#define COMP_ITERS (WORK / THREADS)               // 12
#define COMP_REM (WORK - COMP_ITERS * THREADS)    // 48

extern __shared__ float4 srow[];                  // 6240 float4 = 99840 B

__device__ __forceinline__ void cp_async16(float4* s, const float4* g)
{
    unsigned saddr = (unsigned)__cvta_generic_to_shared(s);
    asm volatile("cp.async.cg.shared.global [%0], [%1], 16;\n"
                 :: "r"(saddr), "l"(g));
}

__global__ __launch_bounds__(THREADS)
void ffm_pair_dot_kernel(const float* __restrict__ in, float* __restrict__ out)
{
    __shared__ unsigned int pair_tab[NPAIRS];     // (fA*4) | (fB*4 << 16)
    __shared__ float warp_sums[THREADS / 32];

    const int tid = threadIdx.x;
    const float4* __restrict__ grow =
        reinterpret_cast<const float4*>(in) + (size_t)blockIdx.x * ROW_F4;

    // ---- phase 1: issue sequential row copy into smem (LDGSTS) ----
    {
        int e4 = tid;
        #pragma unroll
        for (int it = 0; it < LOAD_ITERS; ++it, e4 += THREADS)
            cp_async16(&srow[e4], &grow[e4]);
        if (tid < LOAD_REM)
            cp_async16(&srow[e4], &grow[e4]);
        asm volatile("cp.async.commit_group;\n" ::: "memory");
    }

    // ---- build pair table while copies are in flight (ALU only) ----
    for (int s = tid; s < NPAIRS; s += THREADS) {
        int i = (int)(39.5f - 0.5f * sqrtf((float)(6241 - 8 * s)));
        int c = 39 * i - ((i * (i - 1)) >> 1);            // cum(i)
        if (c > s)                  { --i; c -= (39 - i); }
        else if (c + (39 - i) <= s) { c += (39 - i); ++i; }
        const int j  = i + (s - c);                       // j in [i, 38]
        const int fA = i * COLS + j;
        const int fB = (j + 1) * COLS + i;
        pair_tab[s] = (unsigned int)(fA * 4) | ((unsigned int)(fB * 4) << 16);
    }

    asm volatile("cp.async.wait_group 0;\n" ::: "memory");
    __syncthreads();

    // ---- phase 2: pair-gather dot product from smem ----
    float acc = 0.0f;
    int w = tid;
    #pragma unroll
    for (int it = 0; it < COMP_ITERS; ++it, w += THREADS) {
        const int s  = w >> 2;
        const int d4 = w & 3;
        const unsigned int pk = pair_tab[s];
        const int eA = (int)(pk & 0xffffu) + d4;
        const int eB = (int)(pk >> 16) + d4;

        const float4 a = srow[eA];
        const float4 p = srow[eB];
        acc = fmaf(a.x, p.x, acc);
        acc = fmaf(a.y, p.y, acc);
        acc = fmaf(a.z, p.z, acc);
        acc = fmaf(a.w, p.w, acc);
    }
    if (tid < COMP_REM) {
        const int s  = w >> 2;
        const int d4 = w & 3;
        const unsigned int pk = pair_tab[s];
        const int eA = (int)(pk & 0xffffu) + d4;
        const int eB = (int)(pk >> 16) + d4;

        const float4 a = srow[eA];
        const float4 p = srow[eB];
        acc = fmaf(a.x, p.x, acc);
        acc = fmaf(a.y, p.y, acc);
        acc = fmaf(a.z, p.z, acc);
        acc = fmaf(a.w, p.w, acc);
    }

    // ---- block reduction ----
    #pragma unroll
    for (int o = 16; o > 0; o >>= 1)
        acc += __shfl_down_sync(0xffffffffu, acc, o);

    if ((tid & 31) == 0)
        warp_sums[tid >> 5] = acc;
    __syncthreads();

    if (tid < (THREADS / 32)) {
        acc = warp_sums[tid];
        #pragma unroll
        for (int o = (THREADS / 64); o > 0; o >>= 1)
            acc += __shfl_down_sync(0x000000ffu, acc, o);
        if (tid == 0)
            out[blockIdx.x] = acc;
    }
}

extern "C" void kernel_launch(void* const* d_in, const int* in_sizes, int n_in,
                              void* d_out, int out_size)
{
    const float* in = (const float*)d_in[0];
    float* out = (float*)d_out;
    const int bs = in_sizes[0] / ROW_FLOATS;   // 2048

    cudaFuncSetAttribute(ffm_pair_dot_kernel,
                         cudaFuncAttributeMaxDynamicSharedMemorySize, ROW_BYTES);
    ffm_pair_dot_kernel<<<bs, THREADS, ROW_BYTES>>>(in, out);
}

// round 6
// speedup vs baseline: 1.0240x; 1.0240x over previous
#include <cuda_runtime.h>
#include <cuda_bf16.h>

// FieldAwareFM: out[b] = sum over 780 field pairs (a<b) of
//   dot(x[b, a, b-1, :], x[b, b, a, :]),  x = input reshaped (bs, 40, 39, 16).
//
// R6: TMA bulk pipeline. Thread 0 issues ALL 10 cp.async.bulk chunks (4
// fields = 9984 B each) of the row up-front, each completing on its own
// mbarrier. The copy engine streams the row continuously -- DRAM issue is
// fully decoupled from warp execution (R1-R5 all plateaued at ~5.5 TB/s with
// bursty load issue / phase barriers). Compute overlaps with the stream via
// triangular availability: after chunk c (fields <= 4c+3), all pairs (a,b)
// with b <= 4c+3 are ready. Pair table is sorted by max-field b so each
// pipeline stage consumes a contiguous range.

#define NUM_FIELDS 40
#define COLS 39
#define EMB 16
#define ROW_FLOATS (NUM_FIELDS * COLS * EMB)      // 24960
#define ROW_F4 (ROW_FLOATS / 4)                   // 6240
#define ROW_BYTES (ROW_F4 * 16)                   // 99840
#define FIELD_BYTES (COLS * EMB * 4)              // 2496
#define NPAIRS 780
#define NCHUNKS 10
#define FIELDS_PER_CHUNK 4
#define CHUNK_BYTES (FIELDS_PER_CHUNK * FIELD_BYTES)   // 9984
#define THREADS 256

extern __shared__ float4 srow[];                  // 6240 float4 = 99840 B

__global__ __launch_bounds__(THREADS)
void ffm_pair_dot_kernel(const float* __restrict__ in, float* __restrict__ out)
{
    // pair_tab sorted by b (max field): s = b*(b-1)/2 + a, a < b.
    __shared__ unsigned int pair_tab[NPAIRS];     // (fA*4) | (fB*4 << 16)
    __shared__ float warp_sums[THREADS / 32];
    __shared__ __align__(8) unsigned long long mbar[NCHUNKS];

    const int tid = threadIdx.x;
    const char* grow = (const char*)in + (size_t)blockIdx.x * ROW_BYTES;

    // ---- init barriers (thread 0) ----
    if (tid == 0) {
        #pragma unroll
        for (int c = 0; c < NCHUNKS; ++c) {
            unsigned m = (unsigned)__cvta_generic_to_shared(&mbar[c]);
            asm volatile("mbarrier.init.shared.b64 [%0], %1;"
                         :: "r"(m), "r"(1) : "memory");
        }
    }

    // ---- build pair table (ALU, overlaps with everything) ----
    for (int s = tid; s < NPAIRS; s += THREADS) {
        int b = (int)((1.0f + sqrtf((float)(8 * s + 1))) * 0.5f);
        if (b * (b - 1) / 2 > s)            --b;
        else if ((b + 1) * b / 2 <= s)      ++b;
        const int a  = s - b * (b - 1) / 2;           // a < b
        const int fA = a * COLS + (b - 1);            // x[a][b-1]
        const int fB = b * COLS + a;                  // x[b][a]
        pair_tab[s] = (unsigned int)(fA * 4) | ((unsigned int)(fB * 4) << 16);
    }

    __syncthreads();   // barriers + table visible to all

    // ---- issue the whole row as 10 bulk copies (thread 0 only) ----
    if (tid == 0) {
        #pragma unroll
        for (int c = 0; c < NCHUNKS; ++c) {
            unsigned m = (unsigned)__cvta_generic_to_shared(&mbar[c]);
            unsigned d = (unsigned)__cvta_generic_to_shared(
                             (char*)srow + c * CHUNK_BYTES);
            asm volatile("mbarrier.arrive.expect_tx.shared.b64 _, [%0], %1;"
                         :: "r"(m), "r"(CHUNK_BYTES) : "memory");
            asm volatile(
                "cp.async.bulk.shared::cta.global.mbarrier::complete_tx::bytes"
                " [%0], [%1], %2, [%3];"
                :: "r"(d), "l"(grow + (size_t)c * CHUNK_BYTES),
                   "r"(CHUNK_BYTES), "r"(m) : "memory");
        }
    }

    // ---- staged compute: stage c handles pairs with b in [4c, 4c+4) ----
    float acc = 0.0f;
    int done_items = 0;   // 4 * C(4c, 2)
    #pragma unroll
    for (int c = 0; c < NCHUNKS; ++c) {
        // wait chunk c (monotone: chunks 0..c-1 already waited)
        {
            unsigned m = (unsigned)__cvta_generic_to_shared(&mbar[c]);
            unsigned done;
            asm volatile(
                "{\n\t.reg .pred p;\n\t"
                "mbarrier.try_wait.parity.acquire.cta.shared::cta.b64 p, [%1], 0;\n\t"
                "selp.b32 %0, 1, 0, p;\n\t}"
                : "=r"(done) : "r"(m) : "memory");
            if (!done) {
                asm volatile(
                    "{\n\t.reg .pred P1;\n\t"
                    "W_%=:\n\t"
                    "mbarrier.try_wait.parity.acquire.cta.shared::cta.b64 P1, [%0], 0, 0x989680;\n\t"
                    "@P1 bra.uni D_%=;\n\t"
                    "bra.uni W_%=;\n\t"
                    "D_%=:\n\t}"
                    :: "r"(m) : "memory");
            }
        }

        const int bmax = FIELDS_PER_CHUNK * c + FIELDS_PER_CHUNK;   // 4c+4
        const int end_items = 4 * (bmax * (bmax - 1) / 2);          // 4*C(4c+4,2)

        for (int w = done_items + tid; w < end_items; w += THREADS) {
            const int s  = w >> 2;
            const int d4 = w & 3;
            const unsigned int pk = pair_tab[s];
            const int eA = (int)(pk & 0xffffu) + d4;
            const int eB = (int)(pk >> 16) + d4;

            const float4 a = srow[eA];
            const float4 p = srow[eB];
            acc = fmaf(a.x, p.x, acc);
            acc = fmaf(a.y, p.y, acc);
            acc = fmaf(a.z, p.z, acc);
            acc = fmaf(a.w, p.w, acc);
        }
        done_items = end_items;
    }

    // ---- block reduction ----
    #pragma unroll
    for (int o = 16; o > 0; o >>= 1)
        acc += __shfl_down_sync(0xffffffffu, acc, o);

    if ((tid & 31) == 0)
        warp_sums[tid >> 5] = acc;
    __syncthreads();

    if (tid < (THREADS / 32)) {
        acc = warp_sums[tid];
        #pragma unroll
        for (int o = (THREADS / 64); o > 0; o >>= 1)
            acc += __shfl_down_sync(0x000000ffu, acc, o);
        if (tid == 0)
            out[blockIdx.x] = acc;
    }
}

extern "C" void kernel_launch(void* const* d_in, const int* in_sizes, int n_in,
                              void* d_out, int out_size)
{
    const float* in = (const float*)d_in[0];
    float* out = (float*)d_out;
    const int bs = in_sizes[0] / ROW_FLOATS;   // 2048

    cudaFuncSetAttribute(ffm_pair_dot_kernel,
                         cudaFuncAttributeMaxDynamicSharedMemorySize, ROW_BYTES);
    ffm_pair_dot_kernel<<<bs, THREADS, ROW_BYTES>>>(in, out);
}

// round 7
// speedup vs baseline: 1.0746x; 1.0495x over previous
#include <cuda_runtime.h>
#include <cuda_bf16.h>

// FieldAwareFM: out[b] = sum over 780 field pairs (a<b) of
//   dot(x[b, a, b-1, :], x[b, b, a, :]),  x = input reshaped (bs, 40, 39, 16).
//
// R7: persistent, double-buffered TMA pipeline. One block per SM, two full
// 99840-B row buffers in smem. Each block walks rows blockIdx.x + k*grid.
// Prologue enqueues rows 0 and 1; after computing row k the freed buffer is
// immediately re-armed with row k+2, so the SM's copy engine always has an
// outstanding bulk copy: no per-block prologues, no wave transitions, no
// per-chunk stalls (R1-R6 all plateaued at 5.5-5.8 TB/s on per-row blocks).
// Compute (~1560 cyc/row, smem-bound) hides fully under the ~4700-cyc row
// transfer; steady state is a continuous DRAM stream.

#define NUM_FIELDS 40
#define COLS 39
#define EMB 16
#define ROW_FLOATS (NUM_FIELDS * COLS * EMB)      // 24960
#define ROW_F4 (ROW_FLOATS / 4)                   // 6240
#define ROW_BYTES (ROW_F4 * 16)                   // 99840
#define NPAIRS 780
#define WORK (NPAIRS * 4)                         // 3120 float4-pair items
#define THREADS 512
#define COMP_ITERS (WORK / THREADS)               // 6
#define COMP_REM (WORK - COMP_ITERS * THREADS)    // 48

extern __shared__ __align__(128) float4 sbuf[];   // 2 * ROW_F4 float4

__device__ __forceinline__ void tma_issue_row(unsigned mbar_addr,
                                              float4* sdst,
                                              const float4* gsrc)
{
    unsigned d = (unsigned)__cvta_generic_to_shared(sdst);
    asm volatile("mbarrier.arrive.expect_tx.shared.b64 _, [%0], %1;"
                 :: "r"(mbar_addr), "r"(ROW_BYTES) : "memory");
    asm volatile(
        "cp.async.bulk.shared::cta.global.mbarrier::complete_tx::bytes"
        " [%0], [%1], %2, [%3];"
        :: "r"(d), "l"(gsrc), "r"(ROW_BYTES), "r"(mbar_addr) : "memory");
}

__device__ __forceinline__ void mbar_wait(unsigned mbar_addr, unsigned parity)
{
    unsigned done;
    asm volatile(
        "{\n\t.reg .pred p;\n\t"
        "mbarrier.try_wait.parity.acquire.cta.shared::cta.b64 p, [%1], %2;\n\t"
        "selp.b32 %0, 1, 0, p;\n\t}"
        : "=r"(done) : "r"(mbar_addr), "r"(parity) : "memory");
    if (!done) {
        asm volatile(
            "{\n\t.reg .pred P1;\n\t"
            "W_%=:\n\t"
            "mbarrier.try_wait.parity.acquire.cta.shared::cta.b64 P1, [%0], %1, 0x989680;\n\t"
            "@P1 bra.uni D_%=;\n\t"
            "bra.uni W_%=;\n\t"
            "D_%=:\n\t}"
            :: "r"(mbar_addr), "r"(parity) : "memory");
    }
}

__global__ __launch_bounds__(THREADS, 1)
void ffm_persistent_kernel(const float* __restrict__ in,
                           float* __restrict__ out, int nrows)
{
    __shared__ unsigned int pair_tab[NPAIRS];     // (fA*4) | (fB*4 << 16)
    __shared__ float warp_sums[THREADS / 32];
    __shared__ __align__(8) unsigned long long mbar[2];

    const int tid  = threadIdx.x;
    const int nblk = gridDim.x;
    const int myrows = (nrows - blockIdx.x + nblk - 1) / nblk;
    const float4* __restrict__ gin = reinterpret_cast<const float4*>(in);

    if (tid == 0) {
        #pragma unroll
        for (int c = 0; c < 2; ++c) {
            unsigned m = (unsigned)__cvta_generic_to_shared(&mbar[c]);
            asm volatile("mbarrier.init.shared.b64 [%0], %1;"
                         :: "r"(m), "r"(1) : "memory");
        }
    }

    // ---- pair table, built once per block ----
    for (int s = tid; s < NPAIRS; s += THREADS) {
        int b = (int)((1.0f + sqrtf((float)(8 * s + 1))) * 0.5f);
        if (b * (b - 1) / 2 > s)       --b;
        else if ((b + 1) * b / 2 <= s) ++b;
        const int a  = s - b * (b - 1) / 2;           // a < b
        const int fA = a * COLS + (b - 1);            // x[a][b-1]
        const int fB = b * COLS + a;                  // x[b][a]
        pair_tab[s] = (unsigned int)(fA * 4) | ((unsigned int)(fB * 4) << 16);
    }
    __syncthreads();

    const unsigned m0 = (unsigned)__cvta_generic_to_shared(&mbar[0]);
    const unsigned m1 = (unsigned)__cvta_generic_to_shared(&mbar[1]);

    // ---- prologue: enqueue rows 0 and 1 ----
    if (tid == 0) {
        if (myrows > 0)
            tma_issue_row(m0, sbuf, gin + (size_t)blockIdx.x * ROW_F4);
        if (myrows > 1)
            tma_issue_row(m1, sbuf + ROW_F4,
                          gin + (size_t)(blockIdx.x + nblk) * ROW_F4);
    }

    for (int k = 0; k < myrows; ++k) {
        const int cur = k & 1;
        const unsigned parity = (unsigned)((k >> 1) & 1);
        mbar_wait(cur ? m1 : m0, parity);

        const float4* __restrict__ srow = sbuf + cur * ROW_F4;
        float acc = 0.0f;
        int w = tid;
        #pragma unroll
        for (int it = 0; it < COMP_ITERS; ++it, w += THREADS) {
            const int s  = w >> 2;
            const int d4 = w & 3;
            const unsigned int pk = pair_tab[s];
            const float4 a = srow[(int)(pk & 0xffffu) + d4];
            const float4 p = srow[(int)(pk >> 16) + d4];
            acc = fmaf(a.x, p.x, acc);
            acc = fmaf(a.y, p.y, acc);
            acc = fmaf(a.z, p.z, acc);
            acc = fmaf(a.w, p.w, acc);
        }
        if (tid < COMP_REM) {
            const int s  = w >> 2;
            const int d4 = w & 3;
            const unsigned int pk = pair_tab[s];
            const float4 a = srow[(int)(pk & 0xffffu) + d4];
            const float4 p = srow[(int)(pk >> 16) + d4];
            acc = fmaf(a.x, p.x, acc);
            acc = fmaf(a.y, p.y, acc);
            acc = fmaf(a.z, p.z, acc);
            acc = fmaf(a.w, p.w, acc);
        }

        // ---- block reduction for this row ----
        #pragma unroll
        for (int o = 16; o > 0; o >>= 1)
            acc += __shfl_down_sync(0xffffffffu, acc, o);
        if ((tid & 31) == 0)
            warp_sums[tid >> 5] = acc;
        __syncthreads();
        if (tid < (THREADS / 32)) {
            acc = warp_sums[tid];
            #pragma unroll
            for (int o = (THREADS / 64); o > 0; o >>= 1)
                acc += __shfl_down_sync(0x0000ffffu, acc, o);
            if (tid == 0)
                out[blockIdx.x + (size_t)k * nblk] = acc;
        }
        __syncthreads();   // all threads done with buffer cur + warp_sums

        // ---- refill freed buffer with row k+2 ----
        if (tid == 0 && k + 2 < myrows)
            tma_issue_row(cur ? m1 : m0, sbuf + cur * ROW_F4,
                          gin + (size_t)(blockIdx.x + (size_t)(k + 2) * nblk) * ROW_F4);
    }
}

extern "C" void kernel_launch(void* const* d_in, const int* in_sizes, int n_in,
                              void* d_out, int out_size)
{
    const float* in = (const float*)d_in[0];
    float* out = (float*)d_out;
    const int bs = in_sizes[0] / ROW_FLOATS;   // 2048

    int sms = 148;
    cudaDeviceGetAttribute(&sms, cudaDevAttrMultiProcessorCount, 0);

    cudaFuncSetAttribute(ffm_persistent_kernel,
                         cudaFuncAttributeMaxDynamicSharedMemorySize,
                         2 * ROW_BYTES);
    ffm_persistent_kernel<<<sms, THREADS, 2 * ROW_BYTES>>>(in, out, bs);
}